// round 1
// baseline (speedup 1.0000x reference)
#include <cuda_runtime.h>
#include <math.h>

#define CC 256
#define NT 4096
#define BB 8
#define TQ 64
#define TK 64
#define VSTR 260   // padded V row stride (floats), %4==0 for float4 alignment
#define SSTR 73    // padded S row stride (floats)

// Scratch for Q/K/V projections: 3 x 32MB static device arrays (no allocs).
__device__ float g_q[BB * CC * NT];
__device__ float g_k[BB * CC * NT];
__device__ float g_v[BB * CC * NT];

// ---------------------------------------------------------------------------
// QKV projection: out[b,d,n] = sum_c W[d,c] * X[b,c,n] + bias[d]
// Tiled GEMM: 64(d) x 64(n) tile per block, K-chunks of 16, 4x4 microtile.
// ---------------------------------------------------------------------------
__global__ __launch_bounds__(256) void qkv_kernel(
    const float* __restrict__ x, const float* __restrict__ mo,
    const float* __restrict__ wq, const float* __restrict__ bq,
    const float* __restrict__ wk, const float* __restrict__ bk,
    const float* __restrict__ wv, const float* __restrict__ bv)
{
    const int which = blockIdx.z % 3;
    const int b = blockIdx.z / 3;
    const float* X; const float* W; const float* bias; float* out;
    if (which == 0)      { X = x;  W = wq; bias = bq; out = g_q; }
    else if (which == 1) { X = mo; W = wk; bias = bk; out = g_k; }
    else                 { X = mo; W = wv; bias = bv; out = g_v; }
    X   += (size_t)b * CC * NT;
    out += (size_t)b * CC * NT;

    const int d0 = blockIdx.y * 64;
    const int n0 = blockIdx.x * 64;

    __shared__ float Ws[16][68];  // [kc][d], padded
    __shared__ float Xs[16][64];  // [kc][n]

    const int t  = threadIdx.x;
    const int td = t >> 4, tn = t & 15;

    float acc[4][4] = {};

    for (int c0 = 0; c0 < CC; c0 += 16) {
        {
            const int dd = t >> 2, cq = t & 3;
            float4 w4 = *(const float4*)&W[(size_t)(d0 + dd) * CC + c0 + cq * 4];
            Ws[cq * 4 + 0][dd] = w4.x;
            Ws[cq * 4 + 1][dd] = w4.y;
            Ws[cq * 4 + 2][dd] = w4.z;
            Ws[cq * 4 + 3][dd] = w4.w;
            const int kc = t >> 4, n4 = t & 15;
            *(float4*)&Xs[kc][n4 * 4] =
                *(const float4*)&X[(size_t)(c0 + kc) * NT + n0 + n4 * 4];
        }
        __syncthreads();
        #pragma unroll
        for (int kc = 0; kc < 16; kc++) {
            float4 a  = *(const float4*)&Ws[kc][td * 4];
            float4 bx = *(const float4*)&Xs[kc][tn * 4];
            const float av[4] = {a.x, a.y, a.z, a.w};
            const float bvv[4] = {bx.x, bx.y, bx.z, bx.w};
            #pragma unroll
            for (int i = 0; i < 4; i++)
                #pragma unroll
                for (int j = 0; j < 4; j++)
                    acc[i][j] += av[i] * bvv[j];
        }
        __syncthreads();
    }

    #pragma unroll
    for (int i = 0; i < 4; i++) {
        const float bi = bias[d0 + td * 4 + i];
        float4 r = make_float4(acc[i][0] + bi, acc[i][1] + bi,
                               acc[i][2] + bi, acc[i][3] + bi);
        *(float4*)&out[(size_t)(d0 + td * 4 + i) * NT + n0 + tn * 4] = r;
    }
}

// ---------------------------------------------------------------------------
// Flash attention over channel-major Q/K/V [C, N].
// Block = (batch, 64-query tile). 256 threads.
//   S-phase: S[64q,64k] = Q_tile^T K_tile (16x16 threads, 4x4 microtile)
//   softmax: online (running max m, denom l, correction factor)
//   O-phase: O[256c,64q] += V_tile P^T (32x8 threads, (4+4)c x 8q microtile)
// ---------------------------------------------------------------------------
__global__ __launch_bounds__(256, 1) void attn_kernel(float* __restrict__ gout)
{
    extern __shared__ float sm[];
    float* Qs = sm;                        // [256][64]
    float* Ks = Qs + CC * TQ;              // [256][64]
    float* Vs = Ks + CC * TK;              // [64][VSTR] (transposed: [k][c])
    float* Ss = Vs + TK * VSTR;            // [64][SSTR]
    float* mS = Ss + TQ * SSTR;            // [64]
    float* lS = mS + TQ;                   // [64]
    float* cS = lS + TQ;                   // [64]

    const int b  = blockIdx.y;
    const int i0 = blockIdx.x * TQ;
    const int t  = threadIdx.x;

    const float* q = g_q + (size_t)b * CC * NT;
    const float* k = g_k + (size_t)b * CC * NT;
    const float* v = g_v + (size_t)b * CC * NT;

    // Load Q tile [C][TQ]
    {
        const int fl4 = t & 15, row0 = t >> 4;
        for (int r = row0; r < CC; r += 16)
            *(float4*)&Qs[r * TQ + fl4 * 4] =
                *(const float4*)&q[(size_t)r * NT + i0 + fl4 * 4];
    }
    if (t < TQ) { mS[t] = -1e30f; lS[t] = 0.f; }

    float acc[2][4][8];
    #pragma unroll
    for (int g = 0; g < 2; g++)
        #pragma unroll
        for (int i = 0; i < 4; i++)
            #pragma unroll
            for (int j = 0; j < 8; j++)
                acc[g][i][j] = 0.f;

    const int tq = t >> 4, tk = t & 15;  // S-phase mapping
    const int oq = t >> 5, oc = t & 31;  // O-phase mapping (oq uniform per warp)

    for (int kt = 0; kt < NT / TK; kt++) {
        const int k0 = kt * TK;
        __syncthreads();  // protect Ks/Vs/Ss from previous iteration readers

        // Load K tile [C][TK]
        {
            const int fl4 = t & 15, row0 = t >> 4;
            for (int r = row0; r < CC; r += 16)
                *(float4*)&Ks[r * TK + fl4 * 4] =
                    *(const float4*)&k[(size_t)r * NT + k0 + fl4 * 4];
        }
        // Load V tile transposed: Vs[kk][c]
        {
            const int kk = t & 63, cr0 = t >> 6;
            for (int r = cr0; r < CC; r += 4)
                Vs[kk * VSTR + r] = v[(size_t)r * NT + k0 + kk];
        }
        __syncthreads();

        // S = scale * Q^T K
        float s[4][4] = {};
        #pragma unroll 4
        for (int c = 0; c < CC; c++) {
            float4 a  = *(const float4*)&Qs[c * TQ + tq * 4];
            float4 bx = *(const float4*)&Ks[c * TK + tk * 4];
            const float av[4] = {a.x, a.y, a.z, a.w};
            const float kv[4] = {bx.x, bx.y, bx.z, bx.w};
            #pragma unroll
            for (int i = 0; i < 4; i++)
                #pragma unroll
                for (int j = 0; j < 4; j++)
                    s[i][j] += av[i] * kv[j];
        }
        #pragma unroll
        for (int i = 0; i < 4; i++)
            #pragma unroll
            for (int j = 0; j < 4; j++)
                Ss[(tq * 4 + i) * SSTR + tk * 4 + j] = s[i][j] * 0.0625f;
        __syncthreads();

        // Online softmax per row (4 threads per row, quad shfl reductions)
        {
            const int qr = t >> 2, sub = t & 3;
            float* row = &Ss[qr * SSTR];
            float mx = -1e30f;
            for (int kk = sub; kk < TK; kk += 4) mx = fmaxf(mx, row[kk]);
            mx = fmaxf(mx, __shfl_xor_sync(0xffffffffu, mx, 1));
            mx = fmaxf(mx, __shfl_xor_sync(0xffffffffu, mx, 2));
            const float mold = mS[qr];
            const float mnew = fmaxf(mold, mx);
            float sum = 0.f;
            for (int kk = sub; kk < TK; kk += 4) {
                const float e = __expf(row[kk] - mnew);
                row[kk] = e;
                sum += e;
            }
            sum += __shfl_xor_sync(0xffffffffu, sum, 1);
            sum += __shfl_xor_sync(0xffffffffu, sum, 2);
            if (sub == 0) {
                const float corr = __expf(mold - mnew);
                cS[qr] = corr;
                lS[qr] = lS[qr] * corr + sum;
                mS[qr] = mnew;
            }
        }
        __syncthreads();

        // Rescale accumulators by correction factor
        {
            float cr[8];
            #pragma unroll
            for (int j = 0; j < 8; j++) cr[j] = cS[oq * 8 + j];
            #pragma unroll
            for (int g = 0; g < 2; g++)
                #pragma unroll
                for (int i = 0; i < 4; i++)
                    #pragma unroll
                    for (int j = 0; j < 8; j++)
                        acc[g][i][j] *= cr[j];
        }

        // O += V P^T
        #pragma unroll 2
        for (int kk = 0; kk < TK; kk++) {
            float4 v0 = *(const float4*)&Vs[kk * VSTR + oc * 4];
            float4 v1 = *(const float4*)&Vs[kk * VSTR + 128 + oc * 4];
            float p[8];
            #pragma unroll
            for (int j = 0; j < 8; j++) p[j] = Ss[(oq * 8 + j) * SSTR + kk];
            #pragma unroll
            for (int j = 0; j < 8; j++) {
                acc[0][0][j] += v0.x * p[j];
                acc[0][1][j] += v0.y * p[j];
                acc[0][2][j] += v0.z * p[j];
                acc[0][3][j] += v0.w * p[j];
                acc[1][0][j] += v1.x * p[j];
                acc[1][1][j] += v1.y * p[j];
                acc[1][2][j] += v1.z * p[j];
                acc[1][3][j] += v1.w * p[j];
            }
        }
    }

    // Normalize and stage into Qs (done with Q) for coalesced output
    {
        float inv[8];
        #pragma unroll
        for (int j = 0; j < 8; j++) inv[j] = 1.f / lS[oq * 8 + j];
        #pragma unroll
        for (int g = 0; g < 2; g++)
            #pragma unroll
            for (int i = 0; i < 4; i++)
                #pragma unroll
                for (int j = 0; j < 8; j++)
                    Qs[(g * 128 + oc * 4 + i) * TQ + oq * 8 + j] =
                        acc[g][i][j] * inv[j];
    }
    __syncthreads();
    {
        const int fl4 = t & 15, row0 = t >> 4;
        float* o = gout + (size_t)b * CC * NT;
        for (int r = row0; r < CC; r += 16)
            *(float4*)&o[(size_t)r * NT + i0 + fl4 * 4] =
                *(const float4*)&Qs[r * TQ + fl4 * 4];
    }
}

extern "C" void kernel_launch(void* const* d_in, const int* in_sizes, int n_in,
                              void* d_out, int out_size)
{
    const float* x  = (const float*)d_in[0];
    const float* mo = (const float*)d_in[1];
    const float* wq = (const float*)d_in[2];
    const float* bq = (const float*)d_in[3];
    const float* wk = (const float*)d_in[4];
    const float* bk = (const float*)d_in[5];
    const float* wv = (const float*)d_in[6];
    const float* bv = (const float*)d_in[7];
    float* out = (float*)d_out;

    dim3 g1(NT / 64, CC / 64, BB * 3);
    qkv_kernel<<<g1, 256>>>(x, mo, wq, bq, wk, bk, wv, bv);

    const size_t smem_bytes =
        (size_t)(CC * TQ + CC * TK + TK * VSTR + TQ * SSTR + 3 * TQ) * sizeof(float);
    cudaFuncSetAttribute(attn_kernel,
                         cudaFuncAttributeMaxDynamicSharedMemorySize,
                         (int)smem_bytes);
    dim3 g2(NT / TQ, BB);
    attn_kernel<<<g2, 256, smem_bytes>>>(out);
}

// round 5
// speedup vs baseline: 3.3525x; 3.3525x over previous
#include <cuda_runtime.h>
#include <cuda_fp16.h>
#include <stdint.h>
#include <math.h>

#define CC 256
#define NT 4096
#define BB 8
#define TQ 64          // queries per CTA
#define TK 64          // keys per tile
#define QSTR 264       // half stride of Q/K/V SMEM rows (528B: 16B-aligned, conflict-free ldmatrix)
#define SB 68          // float stride of S buffer
#define PSTR 72        // half stride of P buffer (144B)

// fp16 scratch, all [b][n][c]; Q pre-scaled by 1/16
__device__ __half g_q[(size_t)BB * NT * CC];
__device__ __half g_k[(size_t)BB * NT * CC];
__device__ __half g_v[(size_t)BB * NT * CC];

// SMEM byte offsets
#define SM_Q   0u
#define SM_K   33792u          // 64*264*2
#define SM_V   67584u
#define SM_S   101376u         // fp32 [64][68]
#define SM_P   118784u         // fp16 [64][72]
#define SM_M   128000u
#define SM_L   128256u
#define SM_C   128512u
#define SMEM_BYTES 128768u

__device__ __forceinline__ uint32_t smem_u32(const void* p) {
    uint32_t a;
    asm("{ .reg .u64 t; cvta.to.shared.u64 t, %1; cvt.u32.u64 %0, t; }" : "=r"(a) : "l"(p));
    return a;
}
__device__ __forceinline__ void ldsm_x4(uint32_t* r, uint32_t a) {
    asm volatile("ldmatrix.sync.aligned.m8n8.x4.shared.b16 {%0,%1,%2,%3}, [%4];"
        : "=r"(r[0]), "=r"(r[1]), "=r"(r[2]), "=r"(r[3]) : "r"(a));
}
__device__ __forceinline__ void ldsm_x2(uint32_t* r, uint32_t a) {
    asm volatile("ldmatrix.sync.aligned.m8n8.x2.shared.b16 {%0,%1}, [%2];"
        : "=r"(r[0]), "=r"(r[1]) : "r"(a));
}
__device__ __forceinline__ void ldsm_x2_t(uint32_t* r, uint32_t a) {
    asm volatile("ldmatrix.sync.aligned.m8n8.x2.trans.shared.b16 {%0,%1}, [%2];"
        : "=r"(r[0]), "=r"(r[1]) : "r"(a));
}
__device__ __forceinline__ void mma16816(float* c, const uint32_t* a, const uint32_t* b) {
    asm volatile("mma.sync.aligned.m16n8k16.row.col.f32.f16.f16.f32 "
        "{%0,%1,%2,%3}, {%4,%5,%6,%7}, {%8,%9}, {%0,%1,%2,%3};"
        : "+f"(c[0]), "+f"(c[1]), "+f"(c[2]), "+f"(c[3])
        : "r"(a[0]), "r"(a[1]), "r"(a[2]), "r"(a[3]), "r"(b[0]), "r"(b[1]));
}

// ---------------------------------------------------------------------------
// QKV projection: FP32 SIMT GEMM, fp16 output [b][n][c]; Q scaled by 1/16
// ---------------------------------------------------------------------------
__global__ __launch_bounds__(256) void qkv_kernel(
    const float* __restrict__ x, const float* __restrict__ mo,
    const float* __restrict__ wq, const float* __restrict__ bq,
    const float* __restrict__ wk, const float* __restrict__ bk,
    const float* __restrict__ wv, const float* __restrict__ bv)
{
    const int which = blockIdx.z % 3;
    const int b = blockIdx.z / 3;
    const float* X; const float* W; const float* bias; __half* out; float sc;
    if (which == 0)      { X = x;  W = wq; bias = bq; out = g_q; sc = 0.0625f; }
    else if (which == 1) { X = mo; W = wk; bias = bk; out = g_k; sc = 1.0f; }
    else                 { X = mo; W = wv; bias = bv; out = g_v; sc = 1.0f; }
    X   += (size_t)b * CC * NT;
    out += (size_t)b * NT * CC;

    const int d0 = blockIdx.y * 64;
    const int n0 = blockIdx.x * 64;

    __shared__ float Ws[16][68];
    __shared__ float Xs[16][64];

    const int t = threadIdx.x;
    const int td = t >> 4, tn = t & 15;
    float acc[4][4] = {};

    for (int c0 = 0; c0 < CC; c0 += 16) {
        {
            const int dd = t >> 2, cq = t & 3;
            float4 w4 = *(const float4*)&W[(size_t)(d0 + dd) * CC + c0 + cq * 4];
            Ws[cq * 4 + 0][dd] = w4.x; Ws[cq * 4 + 1][dd] = w4.y;
            Ws[cq * 4 + 2][dd] = w4.z; Ws[cq * 4 + 3][dd] = w4.w;
            const int kc = t >> 4, n4 = t & 15;
            *(float4*)&Xs[kc][n4 * 4] =
                *(const float4*)&X[(size_t)(c0 + kc) * NT + n0 + n4 * 4];
        }
        __syncthreads();
        #pragma unroll
        for (int kc = 0; kc < 16; kc++) {
            float4 a = *(const float4*)&Ws[kc][td * 4];
            float4 bx = *(const float4*)&Xs[kc][tn * 4];
            const float av[4] = {a.x, a.y, a.z, a.w};
            const float bv2[4] = {bx.x, bx.y, bx.z, bx.w};
            #pragma unroll
            for (int i = 0; i < 4; i++)
                #pragma unroll
                for (int j = 0; j < 4; j++)
                    acc[i][j] += av[i] * bv2[j];
        }
        __syncthreads();
    }

    // transposed fp16 store: out[n][c]
    #pragma unroll
    for (int i = 0; i < 4; i++) {
        const float bi = bias[d0 + td * 4 + i];
        #pragma unroll
        for (int j = 0; j < 4; j++)
            out[(size_t)(n0 + tn * 4 + j) * CC + d0 + td * 4 + i] =
                __float2half_rn((acc[i][j] + bi) * sc);
    }
}

// ---------------------------------------------------------------------------
// HMMA flash attention: 256 threads, 64 queries/CTA, 64-key tiles.
// warp = (rg, half): rg picks 16 query rows; half splits keys (S) / channels (PV).
// ---------------------------------------------------------------------------
__global__ __launch_bounds__(256, 1) void attn_kernel(float* __restrict__ gout)
{
    extern __shared__ __align__(16) char smem[];
    const uint32_t sbase = smem_u32(smem);
    float* Sbuf = (float*)(smem + SM_S);
    float* mS = (float*)(smem + SM_M);
    float* lS = (float*)(smem + SM_L);
    float* cS = (float*)(smem + SM_C);

    const int t = threadIdx.x;
    const int warp = t >> 5, lane = t & 31;
    const int rg = warp >> 1, half_id = warp & 1;
    const int g = lane >> 2, t4 = lane & 3, l16 = lane & 15;
    const int qb = rg * 16;

    const int b = blockIdx.y;
    const int i0 = blockIdx.x * TQ;

    // load Q tile [64][256] -> SMEM rows stride QSTR
    {
        const int row = t >> 2, quarter = t & 3;
        const __half* src = g_q + ((size_t)b * NT + i0 + row) * CC + quarter * 64;
        __half* dst = (__half*)(smem + SM_Q) + row * QSTR + quarter * 64;
        #pragma unroll
        for (int i = 0; i < 8; i++)
            *(uint4*)(dst + i * 8) = *(const uint4*)(src + i * 8);
    }
    if (t < TQ) { mS[t] = -1e30f; lS[t] = 0.f; }

    float oacc[16][4];
    #pragma unroll
    for (int nb = 0; nb < 16; nb++)
        #pragma unroll
        for (int e = 0; e < 4; e++) oacc[nb][e] = 0.f;

    for (int kt = 0; kt < NT / TK; kt++) {
        const int k0 = kt * TK;
        __syncthreads();  // prior-tile readers of Ks/Vs done

        // load K and V tiles [64][256]
        {
            const int row = t >> 2, quarter = t & 3;
            const __half* ksrc = g_k + ((size_t)b * NT + k0 + row) * CC + quarter * 64;
            const __half* vsrc = g_v + ((size_t)b * NT + k0 + row) * CC + quarter * 64;
            __half* kdst = (__half*)(smem + SM_K) + row * QSTR + quarter * 64;
            __half* vdst = (__half*)(smem + SM_V) + row * QSTR + quarter * 64;
            #pragma unroll
            for (int i = 0; i < 8; i++) {
                *(uint4*)(kdst + i * 8) = *(const uint4*)(ksrc + i * 8);
                *(uint4*)(vdst + i * 8) = *(const uint4*)(vsrc + i * 8);
            }
        }
        __syncthreads();

        // S = Q K^T : per warp 16 rows x 32 keys (cb = half*32)
        const int cb = half_id * 32;
        float sacc[4][4];
        #pragma unroll
        for (int nb = 0; nb < 4; nb++)
            #pragma unroll
            for (int e = 0; e < 4; e++) sacc[nb][e] = 0.f;

        #pragma unroll
        for (int ks2 = 0; ks2 < 16; ks2++) {
            uint32_t a[4], bf[2];
            ldsm_x4(a, sbase + SM_Q +
                    (uint32_t)(((qb + l16) * QSTR + ks2 * 16 + (lane >> 4) * 8) * 2));
            #pragma unroll
            for (int nb = 0; nb < 4; nb++) {
                ldsm_x2(bf, sbase + SM_K +
                        (uint32_t)(((cb + nb * 8 + (l16 & 7)) * QSTR +
                                    ks2 * 16 + (l16 >> 3) * 8) * 2));
                mma16816(sacc[nb], a, bf);
            }
        }
        // stash S to SMEM
        #pragma unroll
        for (int nb = 0; nb < 4; nb++) {
            const int col = cb + nb * 8 + t4 * 2;
            Sbuf[(qb + g) * SB + col]         = sacc[nb][0];
            Sbuf[(qb + g) * SB + col + 1]     = sacc[nb][1];
            Sbuf[(qb + g + 8) * SB + col]     = sacc[nb][2];
            Sbuf[(qb + g + 8) * SB + col + 1] = sacc[nb][3];
        }
        __syncthreads();

        // online softmax: 4 threads per row
        {
            const int row = t >> 2, sub = t & 3;
            const float* srow = Sbuf + row * SB;
            const float mold = mS[row];
            float mx = mold;
            #pragma unroll
            for (int i = 0; i < 16; i++) mx = fmaxf(mx, srow[sub + 4 * i]);
            mx = fmaxf(mx, __shfl_xor_sync(0xffffffffu, mx, 1));
            mx = fmaxf(mx, __shfl_xor_sync(0xffffffffu, mx, 2));
            float sum = 0.f;
            __half* prow = (__half*)(smem + SM_P) + row * PSTR;
            #pragma unroll
            for (int i = 0; i < 16; i++) {
                const float e = __expf(srow[sub + 4 * i] - mx);
                sum += e;
                prow[sub + 4 * i] = __float2half_rn(e);
            }
            sum += __shfl_xor_sync(0xffffffffu, sum, 1);
            sum += __shfl_xor_sync(0xffffffffu, sum, 2);
            if (sub == 0) {
                const float corr = __expf(mold - mx);
                cS[row] = corr;
                lS[row] = lS[row] * corr + sum;
                mS[row] = mx;
            }
        }
        __syncthreads();

        // rescale O accum and PV: O[16 q][128 c per half] += P[16][64] V[64][..]
        {
            const float c0 = cS[qb + g], c1 = cS[qb + g + 8];
            #pragma unroll
            for (int nb = 0; nb < 16; nb++) {
                oacc[nb][0] *= c0; oacc[nb][1] *= c0;
                oacc[nb][2] *= c1; oacc[nb][3] *= c1;
            }
        }
        #pragma unroll
        for (int ks2 = 0; ks2 < 4; ks2++) {
            uint32_t a[4], bf[2];
            ldsm_x4(a, sbase + SM_P +
                    (uint32_t)(((qb + l16) * PSTR + ks2 * 16 + (lane >> 4) * 8) * 2));
            #pragma unroll
            for (int nb = 0; nb < 16; nb++) {
                const int cb2 = half_id * 128 + nb * 8;
                ldsm_x2_t(bf, sbase + SM_V +
                          (uint32_t)(((ks2 * 16 + l16) * QSTR + cb2) * 2));
                mma16816(oacc[nb], a, bf);
            }
        }
    }

    __syncthreads();  // all PV reads of Vs done before overwriting smem with sf

    // normalize + stage O^T [c][q] into low SMEM, then coalesced store
    {
        float* sf = (float*)smem;  // [256][68]
        const float inv0 = 1.f / lS[qb + g];
        const float inv1 = 1.f / lS[qb + g + 8];
        #pragma unroll
        for (int nb = 0; nb < 16; nb++) {
            const int col = half_id * 128 + nb * 8 + t4 * 2;
            sf[col * 68 + qb + g]           = oacc[nb][0] * inv0;
            sf[(col + 1) * 68 + qb + g]     = oacc[nb][1] * inv0;
            sf[col * 68 + qb + g + 8]       = oacc[nb][2] * inv1;
            sf[(col + 1) * 68 + qb + g + 8] = oacc[nb][3] * inv1;
        }
        __syncthreads();
        float* obase = gout + (size_t)b * CC * NT + i0;
        #pragma unroll
        for (int pass = 0; pass < 2; pass++) {
            const int c = (t >> 1) + pass * 128;
            const int q0 = (t & 1) * 32;
            #pragma unroll
            for (int i = 0; i < 8; i++)
                *(float4*)&obase[(size_t)c * NT + q0 + i * 4] =
                    *(float4*)&sf[c * 68 + q0 + i * 4];
        }
    }
}

extern "C" void kernel_launch(void* const* d_in, const int* in_sizes, int n_in,
                              void* d_out, int out_size)
{
    const float* x  = (const float*)d_in[0];
    const float* mo = (const float*)d_in[1];
    const float* wq = (const float*)d_in[2];
    const float* bq = (const float*)d_in[3];
    const float* wk = (const float*)d_in[4];
    const float* bk = (const float*)d_in[5];
    const float* wv = (const float*)d_in[6];
    const float* bv = (const float*)d_in[7];
    float* out = (float*)d_out;

    dim3 g1(NT / 64, CC / 64, BB * 3);
    qkv_kernel<<<g1, 256>>>(x, mo, wq, bq, wk, bk, wv, bv);

    cudaFuncSetAttribute(attn_kernel, cudaFuncAttributeMaxDynamicSharedMemorySize,
                         (int)SMEM_BYTES);
    dim3 g2(NT / TQ, BB);
    attn_kernel<<<g2, 256, SMEM_BYTES>>>(out);
}